// round 8
// baseline (speedup 1.0000x reference)
#include <cuda_runtime.h>
#include <math.h>

// Swin stage: B=4, H=W=256, C=96, NH=6, HD=16, WS=8, N=64; 4096 windows.
// Fully fused per-window kernel (LN1+QKV+attn+proj+LN2+MLP), tf32 mma.sync.
// Attention is warp-autonomous: softmax entirely in registers, no CTA barriers.

#define W_ELEMS   221184             // packed tf32 weights, both layers

__device__ float g_w[W_ELEMS];       // packed tf32 weights

// packed-weight offsets (floats)
#define OFF_QKV0   0
#define OFF_QKV1   27648
#define OFF_PROJ0  55296
#define OFF_PROJ1  64512
#define OFF_F1_0   73728
#define OFF_F1_1   110592
#define OFF_F2_0   147456
#define OFF_F2_1   184320

__device__ __forceinline__ unsigned f2tf(float f) {
    unsigned u; asm("cvt.rna.tf32.f32 %0, %1;" : "=r"(u) : "f"(f)); return u;
}
__device__ __forceinline__ float tf32f(float f) {
    return __uint_as_float(f2tf(f));
}
__device__ __forceinline__ void mma_tf32(float* c, const unsigned* a, const unsigned* b) {
    asm volatile(
        "mma.sync.aligned.m16n8k8.row.col.f32.tf32.tf32.f32 "
        "{%0,%1,%2,%3},{%4,%5,%6,%7},{%8,%9},{%0,%1,%2,%3};\n"
        : "+f"(c[0]), "+f"(c[1]), "+f"(c[2]), "+f"(c[3])
        : "r"(a[0]), "r"(a[1]), "r"(a[2]), "r"(a[3]), "r"(b[0]), "r"(b[1]));
}

// ---- weight packer: W(O,K) row-major -> per-fragment tf32 layout ----
__global__ void pack_w(const float* __restrict__ src, float* __restrict__ dst,
                       int O, int K) {
    int idx = blockIdx.x * 256 + threadIdx.x;
    if (idx >= O * K) return;
    int j    = idx & 1;
    int lane = (idx >> 1) & 31;
    int rest = idx >> 6;
    int KS   = K >> 3;
    int kk   = rest % KS;
    int nt   = rest / KS;
    int n = nt * 8 + (lane >> 2);
    int k = kk * 8 + (lane & 3) + j * 4;
    dst[idx] = __uint_as_float(f2tf(src[n * K + k]));
}

// ======================= fused Swin block kernel =======================
// smem (floats): xs[64*100]=6400 | qk[18*64*20]=23040 | P[8*16*68]=8704
//   qk aliased after attention: xres[64*100]=6400 | yb[64*100]=6400
#define SMEM_FLOATS (6400 + 23040 + 8704)

__global__ void __launch_bounds__(256) swin_block(
    const float* __restrict__ xin, float* __restrict__ xout,
    const float* __restrict__ wqkv, const float* __restrict__ qkvb,
    const float* __restrict__ wproj, const float* __restrict__ projb,
    const float* __restrict__ rpb,
    const float* __restrict__ g1, const float* __restrict__ bb1,
    const float* __restrict__ g2, const float* __restrict__ bb2,
    const float* __restrict__ w1p, const float* __restrict__ b1v,
    const float* __restrict__ w2p, const float* __restrict__ b2v,
    int shift)
{
    extern __shared__ float sm[];
    float* xs   = sm;             // 64 x 100 : LN'd x -> attention ctx -> LN2'd xres
    float* qk   = sm + 6400;      // [18][64][20] q,k,v ; later xres + yb
    float* Pbuf = sm + 29440;     // 8 warps x 16 x 68 probs

    const int tid = threadIdx.x, lane = tid & 31, wid = tid >> 5;
    const int g = lane >> 2, tg = lane & 3;
    const int wm = wid >> 1, wn = wid & 1;
    const int m0 = wm * 16;

    const int win = blockIdx.x;
    const int b = win >> 10, wi = win & 1023, wh = wi >> 5, ww = wi & 31;

    // ---------- phase 1: LN1 (4 threads/token) ----------
    {
        int t = tid >> 2, l4 = tid & 3;
        int th = t >> 3, tw = t & 7;
        int h0 = (wh*8 + th + shift) & 255, w0 = (ww*8 + tw + shift) & 255;
        const float* xr = xin + ((size_t)b*65536 + (size_t)h0*256 + w0)*96;
        float vals[24], s = 0.f, ss = 0.f;
        #pragma unroll
        for (int j = 0; j < 24; j++) {
            float v = xr[l4 + 4*j]; vals[j] = v; s += v; ss += v*v;
        }
        s  += __shfl_xor_sync(0xffffffffu, s, 1);
        s  += __shfl_xor_sync(0xffffffffu, s, 2);
        ss += __shfl_xor_sync(0xffffffffu, ss, 1);
        ss += __shfl_xor_sync(0xffffffffu, ss, 2);
        float mean = s * (1.f/96.f);
        float rstd = rsqrtf(ss * (1.f/96.f) - mean*mean + 1e-5f);
        #pragma unroll
        for (int j = 0; j < 24; j++) {
            int c = l4 + 4*j;
            xs[t*100 + c] = tf32f((vals[j]-mean)*rstd*g1[c] + bb1[c]);
        }
    }
    __syncthreads();

    // ---------- phase 2: QKV GEMM ----------
    {
        unsigned Af[12][4];
        #pragma unroll
        for (int kk = 0; kk < 12; kk++) {
            int base = (m0+g)*100 + kk*8 + tg;
            Af[kk][0] = __float_as_uint(xs[base]);
            Af[kk][1] = __float_as_uint(xs[base + 800]);
            Af[kk][2] = __float_as_uint(xs[base + 4]);
            Af[kk][3] = __float_as_uint(xs[base + 804]);
        }
        for (int s3 = 0; s3 < 3; s3++) {
            float acc[6][4];
            #pragma unroll
            for (int i = 0; i < 6; i++) { acc[i][0]=acc[i][1]=acc[i][2]=acc[i][3]=0.f; }
            for (int kk = 0; kk < 12; kk++) {
                #pragma unroll
                for (int nt = 0; nt < 6; nt++) {
                    int ntg = s3*12 + wn*6 + nt;
                    float2 bv = *(const float2*)&wqkv[((ntg*12 + kk)*32 + lane)*2];
                    unsigned bb[2] = { __float_as_uint(bv.x), __float_as_uint(bv.y) };
                    mma_tf32(acc[nt], Af[kk], bb);
                }
            }
            #pragma unroll
            for (int nt = 0; nt < 6; nt++) {
                #pragma unroll
                for (int i = 0; i < 2; i++) {
                    #pragma unroll
                    for (int j = 0; j < 2; j++) {
                        int ncol = wn*48 + nt*8 + 2*tg + j;
                        int hh = ncol >> 4, d = ncol & 15;
                        int m = m0 + g + i*8;
                        float v = acc[nt][i*2+j] + __ldg(&qkvb[s3*96 + ncol]);
                        if (s3 == 0) v *= 0.25f;
                        qk[(s3*6 + hh)*1280 + m*20 + d] = tf32f(v);
                    }
                }
            }
        }
    }
    __syncthreads();

    // ---------- phase 3: attention, warp-autonomous ----------
    // 24 tasks = 6 heads x 4 row-blocks; warp w does tasks w, w+8, w+16.
    {
        float* Pw = Pbuf + wid * 1088;   // 16 x 68
        #pragma unroll
        for (int it = 0; it < 3; it++) {
            int task = it*8 + wid;
            int h = task >> 2, r = task & 3;
            int row0 = r * 16;
            const float* qh = qk + h*1280;
            const float* kh = qk + (6+h)*1280;
            const float* vh = qk + (12+h)*1280;

            // scores: full 16 x 64 rows in this warp
            unsigned Aq[2][4];
            #pragma unroll
            for (int kk = 0; kk < 2; kk++) {
                int base = (row0+g)*20 + kk*8 + tg;
                Aq[kk][0] = __float_as_uint(qh[base]);
                Aq[kk][1] = __float_as_uint(qh[base + 160]);
                Aq[kk][2] = __float_as_uint(qh[base + 4]);
                Aq[kk][3] = __float_as_uint(qh[base + 164]);
            }
            float acc[8][4];
            #pragma unroll
            for (int i = 0; i < 8; i++) { acc[i][0]=acc[i][1]=acc[i][2]=acc[i][3]=0.f; }
            #pragma unroll
            for (int kk = 0; kk < 2; kk++) {
                #pragma unroll
                for (int nt = 0; nt < 8; nt++) {
                    unsigned bb[2] = {
                        __float_as_uint(kh[(nt*8+g)*20 + kk*8 + tg]),
                        __float_as_uint(kh[(nt*8+g)*20 + kk*8 + tg + 4]) };
                    mma_tf32(acc[nt], Aq[kk], bb);
                }
            }
            // bias + mask
            #pragma unroll
            for (int nt = 0; nt < 8; nt++) {
                #pragma unroll
                for (int i = 0; i < 2; i++) {
                    #pragma unroll
                    for (int j = 0; j < 2; j++) {
                        int t = row0 + g + i*8;
                        int u = nt*8 + 2*tg + j;
                        int ti = t>>3, tj = t&7, ui = u>>3, uj = u&7;
                        float d = acc[nt][i*2+j]
                                + __ldg(&rpb[((ti-ui+7)*15 + (tj-uj+7))*6 + h]);
                        if (shift) {
                            int hrt = wh*8+ti, wrt = ww*8+tj;
                            int hru = wh*8+ui, wru = ww*8+uj;
                            int rt = (hrt<248?0:(hrt<252?1:2))*3 + (wrt<248?0:(wrt<252?1:2));
                            int ru = (hru<248?0:(hru<252?1:2))*3 + (wru<248?0:(wru<252?1:2));
                            if (rt != ru) d -= 100.f;
                        }
                        acc[nt][i*2+j] = d;
                    }
                }
            }
            // softmax per row (row = row0+g+i*8); 64 cols live in 4 tg-lanes
            #pragma unroll
            for (int i = 0; i < 2; i++) {
                float mx = -1e30f;
                #pragma unroll
                for (int nt = 0; nt < 8; nt++) {
                    mx = fmaxf(mx, fmaxf(acc[nt][i*2], acc[nt][i*2+1]));
                }
                mx = fmaxf(mx, __shfl_xor_sync(0xffffffffu, mx, 1));
                mx = fmaxf(mx, __shfl_xor_sync(0xffffffffu, mx, 2));
                float sum = 0.f;
                #pragma unroll
                for (int nt = 0; nt < 8; nt++) {
                    float e0 = __expf(acc[nt][i*2]   - mx);
                    float e1 = __expf(acc[nt][i*2+1] - mx);
                    acc[nt][i*2] = e0; acc[nt][i*2+1] = e1;
                    sum += e0 + e1;
                }
                sum += __shfl_xor_sync(0xffffffffu, sum, 1);
                sum += __shfl_xor_sync(0xffffffffu, sum, 2);
                float inv = 1.f / sum;
                int lr = g + i*8;
                #pragma unroll
                for (int nt = 0; nt < 8; nt++) {
                    Pw[lr*68 + nt*8 + 2*tg]     = tf32f(acc[nt][i*2]   * inv);
                    Pw[lr*68 + nt*8 + 2*tg + 1] = tf32f(acc[nt][i*2+1] * inv);
                }
            }
            __syncwarp();
            // AV: 16 x 16
            float av[2][4];
            av[0][0]=av[0][1]=av[0][2]=av[0][3]=0.f;
            av[1][0]=av[1][1]=av[1][2]=av[1][3]=0.f;
            #pragma unroll
            for (int kk = 0; kk < 8; kk++) {
                int base = g*68 + kk*8 + tg;
                unsigned Ap[4] = {
                    __float_as_uint(Pw[base]),
                    __float_as_uint(Pw[base + 544]),
                    __float_as_uint(Pw[base + 4]),
                    __float_as_uint(Pw[base + 548]) };
                #pragma unroll
                for (int nt = 0; nt < 2; nt++) {
                    unsigned bb[2] = {
                        __float_as_uint(vh[(kk*8+tg)*20   + nt*8 + g]),
                        __float_as_uint(vh[(kk*8+tg+4)*20 + nt*8 + g]) };
                    mma_tf32(av[nt], Ap, bb);
                }
            }
            #pragma unroll
            for (int nt = 0; nt < 2; nt++)
                #pragma unroll
                for (int i = 0; i < 2; i++)
                    #pragma unroll
                    for (int j = 0; j < 2; j++)
                        xs[(row0+g+i*8)*100 + h*16 + nt*8 + 2*tg + j] =
                            tf32f(av[nt][i*2+j]);
            __syncwarp();
        }
    }
    __syncthreads();

    // ---------- phase 4: proj + residual -> xres (smem) ----------
    float* xres = qk;          // 64 x 100, overwrites q/k/v
    float* yb   = qk + 6400;   // 64 x 100, fc1 output chunk
    {
        unsigned Ac[12][4];
        #pragma unroll
        for (int kk = 0; kk < 12; kk++) {
            int base = (m0+g)*100 + kk*8 + tg;
            Ac[kk][0] = __float_as_uint(xs[base]);
            Ac[kk][1] = __float_as_uint(xs[base + 800]);
            Ac[kk][2] = __float_as_uint(xs[base + 4]);
            Ac[kk][3] = __float_as_uint(xs[base + 804]);
        }
        float acc[6][4];
        #pragma unroll
        for (int i = 0; i < 6; i++) { acc[i][0]=acc[i][1]=acc[i][2]=acc[i][3]=0.f; }
        for (int kk = 0; kk < 12; kk++) {
            #pragma unroll
            for (int nt = 0; nt < 6; nt++) {
                int ntg = wn*6 + nt;
                float2 bv = *(const float2*)&wproj[((ntg*12 + kk)*32 + lane)*2];
                unsigned bb[2] = { __float_as_uint(bv.x), __float_as_uint(bv.y) };
                mma_tf32(acc[nt], Ac[kk], bb);
            }
        }
        __syncthreads();   // all warps done reading q/k/v before xres overwrite
        #pragma unroll
        for (int nt = 0; nt < 6; nt++) {
            #pragma unroll
            for (int i = 0; i < 2; i++) {
                int ncol0 = wn*48 + nt*8 + 2*tg;
                int m = m0 + g + i*8;
                int th = m >> 3, tw = m & 7;
                int h0 = (wh*8 + th + shift) & 255;
                int w0 = (ww*8 + tw + shift) & 255;
                size_t row = ((size_t)b*65536 + (size_t)h0*256 + w0)*96;
                float2 rr = *(const float2*)&xin[row + ncol0];
                xres[m*100 + ncol0]     = rr.x + acc[nt][i*2]   + __ldg(&projb[ncol0]);
                xres[m*100 + ncol0 + 1] = rr.y + acc[nt][i*2+1] + __ldg(&projb[ncol0+1]);
            }
        }
    }
    __syncthreads();

    // ---------- phase 5: LN2 ----------
    {
        int t = tid >> 2, l4 = tid & 3;
        float vals[24], s = 0.f, ss = 0.f;
        #pragma unroll
        for (int j = 0; j < 24; j++) {
            float v = xres[t*100 + l4 + 4*j]; vals[j] = v; s += v; ss += v*v;
        }
        s  += __shfl_xor_sync(0xffffffffu, s, 1);
        s  += __shfl_xor_sync(0xffffffffu, s, 2);
        ss += __shfl_xor_sync(0xffffffffu, ss, 1);
        ss += __shfl_xor_sync(0xffffffffu, ss, 2);
        float mean = s * (1.f/96.f);
        float rstd = rsqrtf(ss * (1.f/96.f) - mean*mean + 1e-5f);
        #pragma unroll
        for (int j = 0; j < 24; j++) {
            int c = l4 + 4*j;
            xs[t*100 + c] = tf32f((vals[j]-mean)*rstd*g2[c] + bb2[c]);
        }
    }
    __syncthreads();

    // ---------- phase 6: MLP ----------
    {
        unsigned Af[12][4];
        #pragma unroll
        for (int kk = 0; kk < 12; kk++) {
            int base = (m0+g)*100 + kk*8 + tg;
            Af[kk][0] = __float_as_uint(xs[base]);
            Af[kk][1] = __float_as_uint(xs[base + 800]);
            Af[kk][2] = __float_as_uint(xs[base + 4]);
            Af[kk][3] = __float_as_uint(xs[base + 804]);
        }
        float acc2[6][4];
        #pragma unroll
        for (int i = 0; i < 6; i++) { acc2[i][0]=acc2[i][1]=acc2[i][2]=acc2[i][3]=0.f; }

        for (int ch = 0; ch < 4; ch++) {
            float acc[6][4];
            #pragma unroll
            for (int i = 0; i < 6; i++) { acc[i][0]=acc[i][1]=acc[i][2]=acc[i][3]=0.f; }
            for (int kk = 0; kk < 12; kk++) {
                #pragma unroll
                for (int nt = 0; nt < 6; nt++) {
                    int ntg = ch*12 + wn*6 + nt;
                    float2 bv = *(const float2*)&w1p[((ntg*12 + kk)*32 + lane)*2];
                    unsigned bb[2] = { __float_as_uint(bv.x), __float_as_uint(bv.y) };
                    mma_tf32(acc[nt], Af[kk], bb);
                }
            }
            #pragma unroll
            for (int nt = 0; nt < 6; nt++) {
                #pragma unroll
                for (int i = 0; i < 2; i++) {
                    #pragma unroll
                    for (int j = 0; j < 2; j++) {
                        int c = wn*48 + nt*8 + 2*tg + j;
                        float v = acc[nt][i*2+j] + __ldg(&b1v[ch*96 + c]);
                        v = v * normcdff(v);
                        yb[(m0+g+i*8)*100 + c] = tf32f(v);
                    }
                }
            }
            __syncthreads();
            for (int kk = 0; kk < 12; kk++) {
                int base = (m0+g)*100 + kk*8 + tg;
                unsigned Ay[4] = {
                    __float_as_uint(yb[base]),
                    __float_as_uint(yb[base + 800]),
                    __float_as_uint(yb[base + 4]),
                    __float_as_uint(yb[base + 804]) };
                #pragma unroll
                for (int nt = 0; nt < 6; nt++) {
                    int ntg = wn*6 + nt;
                    int kkg = ch*12 + kk;
                    float2 bv = *(const float2*)&w2p[((ntg*48 + kkg)*32 + lane)*2];
                    unsigned bb[2] = { __float_as_uint(bv.x), __float_as_uint(bv.y) };
                    mma_tf32(acc2[nt], Ay, bb);
                }
            }
            __syncthreads();
        }

        // final residual writeback (only gmem write of the kernel)
        #pragma unroll
        for (int nt = 0; nt < 6; nt++) {
            #pragma unroll
            for (int i = 0; i < 2; i++) {
                int c0 = wn*48 + nt*8 + 2*tg;
                int m = m0 + g + i*8;
                int th = m >> 3, tw = m & 7;
                int h0 = (wh*8 + th + shift) & 255;
                int w0 = (ww*8 + tw + shift) & 255;
                size_t row = ((size_t)b*65536 + (size_t)h0*256 + w0)*96;
                float2 o;
                o.x = xres[m*100 + c0]     + acc2[nt][i*2]   + __ldg(&b2v[c0]);
                o.y = xres[m*100 + c0 + 1] + acc2[nt][i*2+1] + __ldg(&b2v[c0+1]);
                *(float2*)&xout[row + c0] = o;
            }
        }
    }
}

// ======================= launcher =======================
extern "C" void kernel_launch(void* const* d_in, const int* in_sizes, int n_in,
                              void* d_out, int out_size) {
    const float* x    = (const float*)d_in[0];
    const float* qkvw = (const float*)d_in[1];   // (2,288,96)
    const float* qkvb = (const float*)d_in[2];   // (2,288)
    const float* projw= (const float*)d_in[3];   // (2,96,96)
    const float* projb= (const float*)d_in[4];   // (2,96)
    const float* rpb  = (const float*)d_in[5];   // (2,225,6)
    const float* n1w  = (const float*)d_in[6];
    const float* n1b  = (const float*)d_in[7];
    const float* n2w  = (const float*)d_in[8];
    const float* n2b  = (const float*)d_in[9];
    const float* f1w  = (const float*)d_in[10];  // (2,384,96)
    const float* f1b  = (const float*)d_in[11];  // (2,384)
    const float* f2w  = (const float*)d_in[12];  // (2,96,384)
    const float* f2b  = (const float*)d_in[13];  // (2,96)
    float* out = (float*)d_out;

    float* gw = nullptr;  cudaGetSymbolAddress((void**)&gw, g_w);

    // ---- pack weights to tf32 fragment order ----
    pack_w<<<108, 256>>>(qkvw,          gw + OFF_QKV0, 288, 96);
    pack_w<<<108, 256>>>(qkvw + 27648,  gw + OFF_QKV1, 288, 96);
    pack_w<<<36,  256>>>(projw,         gw + OFF_PROJ0, 96, 96);
    pack_w<<<36,  256>>>(projw + 9216,  gw + OFF_PROJ1, 96, 96);
    pack_w<<<144, 256>>>(f1w,           gw + OFF_F1_0, 384, 96);
    pack_w<<<144, 256>>>(f1w + 36864,   gw + OFF_F1_1, 384, 96);
    pack_w<<<144, 256>>>(f2w,           gw + OFF_F2_0, 96, 384);
    pack_w<<<144, 256>>>(f2w + 36864,   gw + OFF_F2_1, 96, 384);

    const int SMEM = SMEM_FLOATS * 4;   // 152576 B
    cudaFuncSetAttribute(swin_block, cudaFuncAttributeMaxDynamicSharedMemorySize, SMEM);

    const int NBLK = 4096;

    // block 0 (shift 0): x -> out ; block 1 (shift 4): out -> out (in-place safe:
    // each CTA reads only its own window tokens before writing them)
    swin_block<<<NBLK, 256, SMEM>>>(x, out,
        gw + OFF_QKV0, qkvb, gw + OFF_PROJ0, projb, rpb,
        n1w, n1b, n2w, n2b, gw + OFF_F1_0, f1b, gw + OFF_F2_0, f2b, 0);
    swin_block<<<NBLK, 256, SMEM>>>(out, out,
        gw + OFF_QKV1, qkvb + 288, gw + OFF_PROJ1, projb + 96, rpb + 225*6,
        n1w + 96, n1b + 96, n2w + 96, n2b + 96,
        gw + OFF_F1_1, f1b + 384, gw + OFF_F2_1, f2b + 96, 4);
}